// round 15
// baseline (speedup 1.0000x reference)
#include <cuda_runtime.h>
#include <cuda_bf16.h>
#include <cuda_fp16.h>
#include <math.h>
#include <stdint.h>

// Problem constants
#define BATCH 8
#define CIN   256
#define NSEQ  4096
#define DKQ   64
#define DOUT  256

// Attention tiling
#define BM 128
#define BK 64
#define NTILES (NSEQ / BK)

// Scratch (device globals)
__device__ float    g_q[(size_t)BATCH * NSEQ * DKQ];    // [b][n][64], fp32, scaled log2e/8
__device__ uint32_t g_khi[(size_t)BATCH * NSEQ * 32];   // [b][n][32] bf16x2, hi, interleaved
__device__ uint32_t g_klo[(size_t)BATCH * NSEQ * 32];   // [b][n][32] bf16x2, lo, interleaved
__device__ uint32_t g_v[(size_t)BATCH * (NSEQ/2) * DOUT]; // [b][kp][ch] fp16x2 (rows 2kp,2kp+1)
__device__ uint32_t g_wh[8 * 384 * 16];                 // W bf16 hi, [chunk][j][16 u32]
__device__ uint32_t g_wl[8 * 384 * 16];                 // W bf16 lo

__device__ __forceinline__ float fast_exp2(float x) {
    float r;
    asm("ex2.approx.ftz.f32 %0, %1;" : "=f"(r) : "f"(x));
    return r;
}
__device__ __forceinline__ uint32_t smem_u32(const void* p) {
    uint32_t a;
    asm("{ .reg .u64 t; cvta.to.shared.u64 t, %1; cvt.u32.u64 %0, t; }" : "=r"(a) : "l"(p));
    return a;
}
__device__ __forceinline__ void cp_async16(uint32_t dst, const void* src) {
    asm volatile("cp.async.cg.shared.global [%0], [%1], 16;" :: "r"(dst), "l"(src));
}
#define CP_COMMIT() asm volatile("cp.async.commit_group;" ::: "memory")
#define CP_WAIT(N)  asm volatile("cp.async.wait_group %0;" :: "n"(N) : "memory")

// bf16 pack: u32 with first arg in low half
__device__ __forceinline__ uint32_t packbf(float lo, float hi) {
    __nv_bfloat162 h2 = __floats2bfloat162_rn(lo, hi);
    return *(uint32_t*)&h2;
}
__device__ __forceinline__ float bf_lo_f(uint32_t p) { return __uint_as_float(p << 16); }
__device__ __forceinline__ float bf_hi_f(uint32_t p) { return __uint_as_float(p & 0xFFFF0000u); }
// fp16 pack: u32 with first arg in low half
__device__ __forceinline__ uint32_t packh(float lo, float hi) {
    __half2 h2 = __floats2half2_rn(lo, hi);
    return *(uint32_t*)&h2;
}

// fragment interleave position for u32 column index (valid for cu in [0,32))
__device__ __forceinline__ int fpos(int cu) {
    return ((cu >> 3) << 3) + ((cu & 3) << 1) + ((cu >> 2) & 1);
}

// m16n8k16 bf16 mma (QK + proj)
__device__ __forceinline__ void mma16bf(float4& d,
                                        uint32_t a0, uint32_t a1, uint32_t a2, uint32_t a3,
                                        uint32_t b0, uint32_t b1) {
    asm("mma.sync.aligned.m16n8k16.row.col.f32.bf16.bf16.f32 "
        "{%0,%1,%2,%3}, {%4,%5,%6,%7}, {%8,%9}, {%0,%1,%2,%3};"
        : "+f"(d.x), "+f"(d.y), "+f"(d.z), "+f"(d.w)
        : "r"(a0), "r"(a1), "r"(a2), "r"(a3), "r"(b0), "r"(b1));
}
// m16n8k16 fp16 mma (PV)
__device__ __forceinline__ void mma16h(float4& d,
                                       uint32_t a0, uint32_t a1, uint32_t a2, uint32_t a3,
                                       uint32_t b0, uint32_t b1) {
    asm("mma.sync.aligned.m16n8k16.row.col.f32.f16.f16.f32 "
        "{%0,%1,%2,%3}, {%4,%5,%6,%7}, {%8,%9}, {%0,%1,%2,%3};"
        : "+f"(d.x), "+f"(d.y), "+f"(d.z), "+f"(d.w)
        : "r"(a0), "r"(a1), "r"(a2), "r"(a3), "r"(b0), "r"(b1));
}

// ==================== W prep: fp32 -> bf16 hi/lo fragment layout ====================
__global__ __launch_bounds__(256) void w_prep(const float* __restrict__ Wq,
                                              const float* __restrict__ Wk,
                                              const float* __restrict__ Wv) {
    int i = blockIdx.x * 256 + threadIdx.x;   // 49152 tasks
    int cu = i & 15;
    int j  = (i >> 4) % 384;
    int ch = i / 6144;
    int c  = ch * 32 + 2 * cu;

    const float* wrow;
    float s;
    if (j < 64)       { wrow = Wq + (size_t)j * CIN;        s = 0.125f * 1.4426950408889634f; }
    else if (j < 128) { wrow = Wk + (size_t)(j - 64) * CIN; s = 1.0f; }
    else              { wrow = Wv + (size_t)(j - 128) * CIN; s = 1.0f; }

    float va = wrow[c] * s;
    float vb = wrow[c + 1] * s;
    uint32_t h = packbf(va, vb);
    uint32_t l = packbf(va - bf_lo_f(h), vb - bf_hi_f(h));
    size_t dst = ((size_t)ch * 384 + j) * 16 + fpos(cu);
    g_wh[dst] = h;
    g_wl[dst] = l;
}

// ==================== tensor-core projection ====================
// SMEM (u32): swh [384][24] @0, swl @9216, sxh [64][24] @18432, sxl @19968.
#define PW_H 0
#define PW_L 9216
#define PX_H 18432
#define PX_L 19968
#define PROJ_SMEM_U32 21504   // 86016 bytes

__global__ __launch_bounds__(256, 1) void proj_tc(const float* __restrict__ x) {
    extern __shared__ uint32_t su[];
    uint32_t* swh = su + PW_H;
    uint32_t* swl = su + PW_L;
    uint32_t* sxh = su + PX_H;
    uint32_t* sxl = su + PX_L;
    const uint32_t smb = smem_u32(su);

    const int tid = threadIdx.x;
    const int w   = tid >> 5;
    const int ln  = tid & 31;
    const int l4  = ln >> 2;
    const int lm4 = ln & 3;
    const int wr  = w & 3;
    const int jh  = w >> 2;
    const int b   = blockIdx.y;
    const int n0  = blockIdx.x * 64;

    float4 acc[24];
    #pragma unroll
    for (int nt = 0; nt < 24; nt++) acc[nt] = make_float4(0.f, 0.f, 0.f, 0.f);

    #pragma unroll 1
    for (int ch = 0; ch < 8; ch++) {
        __syncthreads();

        #pragma unroll
        for (int it = 0; it < 12; it++) {
            int i = tid + it * 256;              // 3072: 2 arrays x 384 rows x 4 q4
            int arr = (i >= 1536);
            int ii  = i - (arr ? 1536 : 0);
            int r   = ii >> 2;
            int q4  = ii & 3;
            const uint32_t* src = (arr ? g_wl : g_wh) + ((size_t)ch * 384 + r) * 16 + q4 * 4;
            uint32_t dst = smb + (uint32_t)((arr ? PW_L : PW_H) + r * 24 + q4 * 4) * 4;
            cp_async16(dst, src);
        }
        CP_COMMIT();

        #pragma unroll
        for (int it = 0; it < 2; it++) {
            int i = tid + it * 256;              // 512 tasks: cu 16 x n2 32
            int cu = i & 15, n2 = i >> 4;
            int c = ch * 32 + 2 * cu;
            const float* xp = x + ((size_t)(b * CIN + c)) * NSEQ + n0 + 2 * n2;
            float2 va = *(const float2*)xp;
            float2 vb = *(const float2*)(xp + NSEQ);
            int pos = fpos(cu);
            uint32_t h0 = packbf(va.x, vb.x);
            uint32_t l0 = packbf(va.x - bf_lo_f(h0), vb.x - bf_hi_f(h0));
            uint32_t h1 = packbf(va.y, vb.y);
            uint32_t l1 = packbf(va.y - bf_lo_f(h1), vb.y - bf_hi_f(h1));
            sxh[(2 * n2) * 24 + pos]     = h0;
            sxl[(2 * n2) * 24 + pos]     = l0;
            sxh[(2 * n2 + 1) * 24 + pos] = h1;
            sxl[(2 * n2 + 1) * 24 + pos] = l1;
        }
        CP_WAIT(0);
        __syncthreads();

        #pragma unroll
        for (int kt = 0; kt < 2; kt++) {
            const int ab = (16 * wr + l4) * 24 + kt * 8 + 2 * lm4;
            uint2 xa = *(const uint2*)&sxh[ab];
            uint2 xb = *(const uint2*)&sxh[ab + 8 * 24];
            uint2 la = *(const uint2*)&sxl[ab];
            uint2 lb = *(const uint2*)&sxl[ab + 8 * 24];
            #pragma unroll
            for (int nt = 0; nt < 24; nt++) {
                const int bc = (jh * 192 + nt * 8 + l4) * 24 + kt * 8 + 2 * lm4;
                uint2 wh2 = *(const uint2*)&swh[bc];
                uint2 wl2 = *(const uint2*)&swl[bc];
                mma16bf(acc[nt], xa.x, xb.x, xa.y, xb.y, wh2.x, wh2.y);
                mma16bf(acc[nt], xa.x, xb.x, xa.y, xb.y, wl2.x, wl2.y);
                mma16bf(acc[nt], la.x, lb.x, la.y, lb.y, wh2.x, wh2.y);
            }
        }
    }

    // ---- epilogue: route to g_q / g_khi+g_klo / g_v(fp16 kpair-packed) ----
    const int r0 = 16 * wr + l4;
    const size_t nrow0 = (size_t)b * NSEQ + n0 + r0;
    const size_t nrow1 = nrow0 + 8;
    // V pair bases (valid when l4 even): rows (r0, r0+1) and (r0+8, r0+9)
    const size_t vb0 = ((size_t)b * (NSEQ / 2) + ((n0 + r0) >> 1)) * DOUT;
    const size_t vb1 = ((size_t)b * (NSEQ / 2) + ((n0 + r0 + 8) >> 1)) * DOUT;
    const bool vwrite = ((l4 & 1) == 0);

    if (jh == 0) {
        #pragma unroll
        for (int nt = 0; nt < 24; nt++) {
            float4 d = acc[nt];
            if (nt < 8) {
                int j = nt * 8 + 2 * lm4;
                *(float2*)&g_q[nrow0 * DKQ + j] = make_float2(d.x, d.y);
                *(float2*)&g_q[nrow1 * DKQ + j] = make_float2(d.z, d.w);
            } else if (nt < 16) {
                int cu = (nt - 8) * 4 + lm4;
                int pos = fpos(cu);
                uint32_t h0 = packbf(d.x, d.y);
                uint32_t l0 = packbf(d.x - bf_lo_f(h0), d.y - bf_hi_f(h0));
                uint32_t h1 = packbf(d.z, d.w);
                uint32_t l1 = packbf(d.z - bf_lo_f(h1), d.w - bf_hi_f(h1));
                g_khi[nrow0 * 32 + pos] = h0;
                g_klo[nrow0 * 32 + pos] = l0;
                g_khi[nrow1 * 32 + pos] = h1;
                g_klo[nrow1 * 32 + pos] = l1;
            } else {
                int o = (nt - 16) * 8 + 2 * lm4;
                float px = __uint_as_float(__shfl_down_sync(0xffffffffu, __float_as_uint(d.x), 4));
                float py = __uint_as_float(__shfl_down_sync(0xffffffffu, __float_as_uint(d.y), 4));
                float pz = __uint_as_float(__shfl_down_sync(0xffffffffu, __float_as_uint(d.z), 4));
                float pw = __uint_as_float(__shfl_down_sync(0xffffffffu, __float_as_uint(d.w), 4));
                if (vwrite) {
                    g_v[vb0 + o]     = packh(d.x, px);
                    g_v[vb0 + o + 1] = packh(d.y, py);
                    g_v[vb1 + o]     = packh(d.z, pz);
                    g_v[vb1 + o + 1] = packh(d.w, pw);
                }
            }
        }
    } else {
        #pragma unroll
        for (int nt = 0; nt < 24; nt++) {
            float4 d = acc[nt];
            int o = 64 + nt * 8 + 2 * lm4;
            float px = __uint_as_float(__shfl_down_sync(0xffffffffu, __float_as_uint(d.x), 4));
            float py = __uint_as_float(__shfl_down_sync(0xffffffffu, __float_as_uint(d.y), 4));
            float pz = __uint_as_float(__shfl_down_sync(0xffffffffu, __float_as_uint(d.z), 4));
            float pw = __uint_as_float(__shfl_down_sync(0xffffffffu, __float_as_uint(d.w), 4));
            if (vwrite) {
                g_v[vb0 + o]     = packh(d.x, px);
                g_v[vb0 + o + 1] = packh(d.y, py);
                g_v[vb1 + o]     = packh(d.z, pz);
                g_v[vb1 + o + 1] = packh(d.w, pw);
            }
        }
    }
}

// ==================== cp.async pipelined flash attention (bf16 QK, fp16 PV) ====================
// SMEM (u32 units):
//   sKh [64][40] @0 (2560), sKl @2560
//   sV  [32][264] @5120 (8448)  -- kpair rows, fp16x2
//   sP  [128][36] @13568 (4608) -- fp16x2 key pairs
//   lrow @18176 (128 f)
// Q staging (prologue only): floats at u32 offset 5120 (size 8704 <= 13056 free)
#define KH_O 0
#define KL_O 2560
#define V_O  5120
#define P_O  13568
#define L_O  18176
#define ATT_SMEM_U32 18304   // 73216 bytes

__device__ __forceinline__ void issue_k(int b, int k0, int tid, uint32_t smb) {
    #pragma unroll
    for (int it = 0; it < 4; it++) {
        int i = tid + it * 256;              // 1024 chunks: 2 arrays x 64 rows x 8
        int arr = i >> 9, r = (i >> 3) & 63, c = i & 7;
        const uint32_t* src = (arr ? g_klo : g_khi) +
                              ((size_t)b * NSEQ + k0 + r) * 32 + c * 4;
        uint32_t dst = smb + (uint32_t)(arr ? KL_O : KH_O) * 4 + r * 160 + c * 16;
        cp_async16(dst, src);
    }
}
__device__ __forceinline__ void issue_v(int b, int k0, int tid, uint32_t smb) {
    const uint32_t* vg = g_v + ((size_t)b * (NSEQ / 2) + k0 / 2) * DOUT;
    #pragma unroll
    for (int it = 0; it < 8; it++) {
        int i = tid + it * 256;              // 2048 chunks: 32 kpair rows x 64
        int r = i >> 6, c4 = i & 63;
        uint32_t dst = smb + (uint32_t)V_O * 4 + r * 1056 + c4 * 16;
        cp_async16(dst, vg + (size_t)r * DOUT + 4 * c4);
    }
}

__global__ __launch_bounds__(256, 1) void attn_mma(float* __restrict__ out) {
    extern __shared__ uint32_t su[];
    const uint32_t* sKh = su + KH_O;
    const uint32_t* sKl = su + KL_O;
    const uint32_t* sVu = su + V_O;
    uint32_t* sPu = su + P_O;
    float* lrow = (float*)(su + L_O);
    float* sQf = (float*)(su + V_O);   // prologue staging
    const uint32_t smb = smem_u32(su);

    const int tid = threadIdx.x;
    const int w   = tid >> 5;
    const int ln  = tid & 31;
    const int l4  = ln >> 2;
    const int lm4 = ln & 3;
    const int rg  = w >> 1;
    const int cg  = w & 1;
    const int b   = blockIdx.y;
    const int n0  = blockIdx.x * BM;

    // K(0) in flight during Q staging (disjoint smem regions)
    issue_k(b, 0, tid, smb);
    CP_COMMIT();

    // ---- stage Q (fp32) through V region, build bf16 hi/lo A-fragments ----
    uint32_t qh[4][4], ql[4][4];
    {
        const float* qg = g_q + ((size_t)b * NSEQ + n0) * DKQ;
        #pragma unroll
        for (int it = 0; it < 8; it++) {
            int i = tid + it * 256;
            int r = i >> 4, c4 = i & 15;
            *(float4*)&sQf[r * 68 + 4 * c4] = *(const float4*)&qg[(size_t)r * DKQ + 4 * c4];
        }
        __syncthreads();
        const int r0 = (w * 16 + l4) * 68;
        const int r1 = r0 + 8 * 68;
        #pragma unroll
        for (int kt = 0; kt < 4; kt++) {
            const int d0 = 16 * kt + 2 * lm4;
            float2 va = *(const float2*)&sQf[r0 + d0];
            float2 vb = *(const float2*)&sQf[r1 + d0];
            float2 vc = *(const float2*)&sQf[r0 + d0 + 8];
            float2 vd = *(const float2*)&sQf[r1 + d0 + 8];
            uint32_t h;
            h = packbf(va.x, va.y); qh[kt][0] = h;
            ql[kt][0] = packbf(va.x - bf_lo_f(h), va.y - bf_hi_f(h));
            h = packbf(vb.x, vb.y); qh[kt][1] = h;
            ql[kt][1] = packbf(vb.x - bf_lo_f(h), vb.y - bf_hi_f(h));
            h = packbf(vc.x, vc.y); qh[kt][2] = h;
            ql[kt][2] = packbf(vc.x - bf_lo_f(h), vc.y - bf_hi_f(h));
            h = packbf(vd.x, vd.y); qh[kt][3] = h;
            ql[kt][3] = packbf(vd.x - bf_lo_f(h), vd.y - bf_hi_f(h));
        }
        __syncthreads();   // done reading staging before V(0) overwrites it
    }
    issue_v(b, 0, tid, smb);
    CP_COMMIT();

    float4 O[32];
    #pragma unroll
    for (int nt = 0; nt < 32; nt++) O[nt] = make_float4(0.f, 0.f, 0.f, 0.f);
    float lsumA = 0.f, lsumB = 0.f;

    const int prow = (w * 16 + l4) * 36;

    #pragma unroll 1
    for (int t = 0; t < NTILES; t++) {
        // K(t) ready (V(t) may still be in flight)
        CP_WAIT(1);
        __syncthreads();

        // ---- S = Qhi*(Khi+Klo) + Qlo*Khi  (bf16x3) ----
        float4 S[8];
        #pragma unroll
        for (int nt = 0; nt < 8; nt++) S[nt] = make_float4(0.f, 0.f, 0.f, 0.f);

        #pragma unroll
        for (int kt = 0; kt < 4; kt++) {
            #pragma unroll
            for (int nt = 0; nt < 8; nt++) {
                const int bc = (nt * 8 + l4) * 40 + kt * 8 + 2 * lm4;
                uint2 kh = *(const uint2*)&sKh[bc];
                uint2 kl = *(const uint2*)&sKl[bc];
                mma16bf(S[nt], qh[kt][0], qh[kt][1], qh[kt][2], qh[kt][3], kh.x, kh.y);
                mma16bf(S[nt], qh[kt][0], qh[kt][1], qh[kt][2], qh[kt][3], kl.x, kl.y);
                mma16bf(S[nt], ql[kt][0], ql[kt][1], ql[kt][2], ql[kt][3], kh.x, kh.y);
            }
        }

        // ---- softmax (log2 domain); P -> fp16 pairs; lsum in fp32 ----
        #pragma unroll
        for (int nt = 0; nt < 8; nt++) {
            float p0 = fast_exp2(S[nt].x);
            float p1 = fast_exp2(S[nt].y);
            float p2 = fast_exp2(S[nt].z);
            float p3 = fast_exp2(S[nt].w);
            lsumA += p0 + p1;
            lsumB += p2 + p3;
            const int pc = prow + nt * 4 + lm4;
            sPu[pc]          = packh(p0, p1);
            sPu[pc + 8 * 36] = packh(p2, p3);
        }
        __syncthreads();   // QK done with K; P visible block-wide

        if (t + 1 < NTILES) issue_k(b, (t + 1) * BK, tid, smb);
        CP_COMMIT();

        // V(t) ready
        CP_WAIT(1);
        __syncthreads();

        // ---- O += P * V (fp16 k16) : rows [32rg,+32) x channels [128cg,+128) ----
        #pragma unroll
        for (int kt = 0; kt < 4; kt++) {
            const int ac0 = (32 * rg + l4) * 36 + 8 * kt + lm4;
            const int ac1 = ac0 + 16 * 36;
            uint32_t pa0 = sPu[ac0],     pa1 = sPu[ac0 + 8 * 36];
            uint32_t pa2 = sPu[ac0 + 4], pa3 = sPu[ac0 + 8 * 36 + 4];
            uint32_t pb0 = sPu[ac1],     pb1 = sPu[ac1 + 8 * 36];
            uint32_t pb2 = sPu[ac1 + 4], pb3 = sPu[ac1 + 8 * 36 + 4];
            const int v0b = (8 * kt + lm4) * 264 + 128 * cg + l4;
            const int v1b = v0b + 4 * 264;
            #pragma unroll
            for (int nt = 0; nt < 16; nt++) {
                uint32_t v0 = sVu[v0b + nt * 8];
                uint32_t v1 = sVu[v1b + nt * 8];
                mma16h(O[nt],      pa0, pa1, pa2, pa3, v0, v1);
                mma16h(O[16 + nt], pb0, pb1, pb2, pb3, v0, v1);
            }
        }
        __syncthreads();   // PV done with V

        if (t + 1 < NTILES) issue_v(b, (t + 1) * BK, tid, smb);
        CP_COMMIT();
    }

    // ---- epilogue ----
    lsumA += __shfl_xor_sync(0xffffffffu, lsumA, 1);
    lsumA += __shfl_xor_sync(0xffffffffu, lsumA, 2);
    lsumB += __shfl_xor_sync(0xffffffffu, lsumB, 1);
    lsumB += __shfl_xor_sync(0xffffffffu, lsumB, 2);
    if (lm4 == 0) {
        lrow[w * 16 + l4]     = lsumA;
        lrow[w * 16 + l4 + 8] = lsumB;
    }
    __syncthreads();

    #pragma unroll
    for (int mb = 0; mb < 2; mb++) {
        const int rbase = 32 * rg + 16 * mb + l4;
        float invA = 1.0f / lrow[rbase];
        float invB = 1.0f / lrow[rbase + 8];
        float* ob = out + (size_t)b * DOUT * NSEQ + n0 + rbase;
        #pragma unroll
        for (int nt = 0; nt < 16; nt++) {
            int o = 128 * cg + nt * 8 + 2 * lm4;
            float4 v = O[mb * 16 + nt];
            ob[(size_t)o * NSEQ]           = v.x * invA;
            ob[(size_t)(o + 1) * NSEQ]     = v.y * invA;
            ob[(size_t)o * NSEQ + 8]       = v.z * invB;
            ob[(size_t)(o + 1) * NSEQ + 8] = v.w * invB;
        }
    }
}

extern "C" void kernel_launch(void* const* d_in, const int* in_sizes, int n_in,
                              void* d_out, int out_size) {
    (void)in_sizes; (void)n_in; (void)out_size;
    const float* x  = (const float*)d_in[0];
    const float* Wq = (const float*)d_in[1];
    const float* Wk = (const float*)d_in[2];
    const float* Wv = (const float*)d_in[3];
    float* out = (float*)d_out;

    cudaFuncSetAttribute(proj_tc, cudaFuncAttributeMaxDynamicSharedMemorySize,
                         PROJ_SMEM_U32 * (int)sizeof(uint32_t));
    cudaFuncSetAttribute(attn_mma, cudaFuncAttributeMaxDynamicSharedMemorySize,
                         ATT_SMEM_U32 * (int)sizeof(uint32_t));

    w_prep<<<192, 256>>>(Wq, Wk, Wv);

    dim3 gp(NSEQ / 64, BATCH);
    proj_tc<<<gp, 256, PROJ_SMEM_U32 * sizeof(uint32_t)>>>(x);

    dim3 ga(NSEQ / BM, BATCH);
    attn_mma<<<ga, 256, ATT_SMEM_U32 * sizeof(uint32_t)>>>(out);
}

// round 16
// speedup vs baseline: 1.0472x; 1.0472x over previous
#include <cuda_runtime.h>
#include <cuda_bf16.h>
#include <cuda_fp16.h>
#include <math.h>
#include <stdint.h>

// Problem constants
#define BATCH 8
#define CIN   256
#define NSEQ  4096
#define DKQ   64
#define DOUT  256

// Attention tiling
#define BM 128
#define BK 64
#define NTILES (NSEQ / BK)

// Scratch (device globals)
__device__ float    g_q[(size_t)BATCH * NSEQ * DKQ];    // [b][n][64], fp32, scaled log2e/8
__device__ uint32_t g_khi[(size_t)BATCH * NSEQ * 32];   // [b][n][32] fp16x2, hi, interleaved
__device__ uint32_t g_klo[(size_t)BATCH * NSEQ * 32];   // [b][n][32] fp16x2, lo, interleaved
__device__ uint32_t g_v[(size_t)BATCH * (NSEQ/2) * DOUT]; // [b][kp][ch] fp16x2 (rows 2kp,2kp+1)
__device__ uint32_t g_wh[8 * 384 * 16];                 // W bf16 hi, [chunk][j][16 u32]
__device__ uint32_t g_wl[8 * 384 * 16];                 // W bf16 lo

__device__ __forceinline__ float fast_exp2(float x) {
    float r;
    asm("ex2.approx.ftz.f32 %0, %1;" : "=f"(r) : "f"(x));
    return r;
}
__device__ __forceinline__ uint32_t smem_u32(const void* p) {
    uint32_t a;
    asm("{ .reg .u64 t; cvta.to.shared.u64 t, %1; cvt.u32.u64 %0, t; }" : "=r"(a) : "l"(p));
    return a;
}
__device__ __forceinline__ void cp_async16(uint32_t dst, const void* src) {
    asm volatile("cp.async.cg.shared.global [%0], [%1], 16;" :: "r"(dst), "l"(src));
}
#define CP_COMMIT() asm volatile("cp.async.commit_group;" ::: "memory")
#define CP_WAIT(N)  asm volatile("cp.async.wait_group %0;" :: "n"(N) : "memory")

// bf16 pack
__device__ __forceinline__ uint32_t packbf(float lo, float hi) {
    __nv_bfloat162 h2 = __floats2bfloat162_rn(lo, hi);
    return *(uint32_t*)&h2;
}
__device__ __forceinline__ float bf_lo_f(uint32_t p) { return __uint_as_float(p << 16); }
__device__ __forceinline__ float bf_hi_f(uint32_t p) { return __uint_as_float(p & 0xFFFF0000u); }
// fp16 pack / extract
__device__ __forceinline__ uint32_t packh(float lo, float hi) {
    __half2 h2 = __floats2half2_rn(lo, hi);
    return *(uint32_t*)&h2;
}
__device__ __forceinline__ float h_lo_f(uint32_t p) {
    return __half2float(__ushort_as_half((unsigned short)(p & 0xFFFFu)));
}
__device__ __forceinline__ float h_hi_f(uint32_t p) {
    return __half2float(__ushort_as_half((unsigned short)(p >> 16)));
}

// fragment interleave position for u32 column index (cu in [0,32))
__device__ __forceinline__ int fpos(int cu) {
    return ((cu >> 3) << 3) + ((cu & 3) << 1) + ((cu >> 2) & 1);
}

// m16n8k16 bf16 mma (proj)
__device__ __forceinline__ void mma16bf(float4& d,
                                        uint32_t a0, uint32_t a1, uint32_t a2, uint32_t a3,
                                        uint32_t b0, uint32_t b1) {
    asm("mma.sync.aligned.m16n8k16.row.col.f32.bf16.bf16.f32 "
        "{%0,%1,%2,%3}, {%4,%5,%6,%7}, {%8,%9}, {%0,%1,%2,%3};"
        : "+f"(d.x), "+f"(d.y), "+f"(d.z), "+f"(d.w)
        : "r"(a0), "r"(a1), "r"(a2), "r"(a3), "r"(b0), "r"(b1));
}
// m16n8k16 fp16 mma (QK + PV)
__device__ __forceinline__ void mma16h(float4& d,
                                       uint32_t a0, uint32_t a1, uint32_t a2, uint32_t a3,
                                       uint32_t b0, uint32_t b1) {
    asm("mma.sync.aligned.m16n8k16.row.col.f32.f16.f16.f32 "
        "{%0,%1,%2,%3}, {%4,%5,%6,%7}, {%8,%9}, {%0,%1,%2,%3};"
        : "+f"(d.x), "+f"(d.y), "+f"(d.z), "+f"(d.w)
        : "r"(a0), "r"(a1), "r"(a2), "r"(a3), "r"(b0), "r"(b1));
}

// ==================== W prep: fp32 -> bf16 hi/lo fragment layout ====================
__global__ __launch_bounds__(256) void w_prep(const float* __restrict__ Wq,
                                              const float* __restrict__ Wk,
                                              const float* __restrict__ Wv) {
    int i = blockIdx.x * 256 + threadIdx.x;   // 49152 tasks
    int cu = i & 15;
    int j  = (i >> 4) % 384;
    int ch = i / 6144;
    int c  = ch * 32 + 2 * cu;

    const float* wrow;
    float s;
    if (j < 64)       { wrow = Wq + (size_t)j * CIN;        s = 0.125f * 1.4426950408889634f; }
    else if (j < 128) { wrow = Wk + (size_t)(j - 64) * CIN; s = 1.0f; }
    else              { wrow = Wv + (size_t)(j - 128) * CIN; s = 1.0f; }

    float va = wrow[c] * s;
    float vb = wrow[c + 1] * s;
    uint32_t h = packbf(va, vb);
    uint32_t l = packbf(va - bf_lo_f(h), vb - bf_hi_f(h));
    size_t dst = ((size_t)ch * 384 + j) * 16 + fpos(cu);
    g_wh[dst] = h;
    g_wl[dst] = l;
}

// ==================== tensor-core projection (128 rows/CTA) ====================
// SMEM (u32): swh [384][24] @0, swl @9216,
//             sxh0 @18432, sxl0 @19968, sxh1 @21504, sxl1 @23040  (each [64][24])
#define PW_H  0
#define PW_L  9216
#define PX_H0 18432
#define PX_L0 19968
#define PX_H1 21504
#define PX_L1 23040
#define PROJ_SMEM_U32 24576   // 98304 bytes

__global__ __launch_bounds__(256, 1) void proj_tc(const float* __restrict__ x) {
    extern __shared__ uint32_t su[];
    uint32_t* swh = su + PW_H;
    uint32_t* swl = su + PW_L;
    const uint32_t smb = smem_u32(su);

    const int tid = threadIdx.x;
    const int w   = tid >> 5;
    const int ln  = tid & 31;
    const int l4  = ln >> 2;
    const int lm4 = ln & 3;
    const int wr  = w & 3;
    const int jh  = w >> 2;
    const int b   = blockIdx.y;
    const int n0  = blockIdx.x * 128;

    float4 acc0[24], acc1[24];
    #pragma unroll
    for (int nt = 0; nt < 24; nt++) {
        acc0[nt] = make_float4(0.f, 0.f, 0.f, 0.f);
        acc1[nt] = make_float4(0.f, 0.f, 0.f, 0.f);
    }

    #pragma unroll 1
    for (int ch = 0; ch < 8; ch++) {
        __syncthreads();

        // ---- issue W chunk cp.async ----
        #pragma unroll
        for (int it = 0; it < 12; it++) {
            int i = tid + it * 256;              // 3072: 2 arrays x 384 rows x 4 q4
            int arr = (i >= 1536);
            int ii  = i - (arr ? 1536 : 0);
            int r   = ii >> 2;
            int q4  = ii & 3;
            const uint32_t* src = (arr ? g_wl : g_wh) + ((size_t)ch * 384 + r) * 16 + q4 * 4;
            uint32_t dst = smb + (uint32_t)((arr ? PW_L : PW_H) + r * 24 + q4 * 4) * 4;
            cp_async16(dst, src);
        }
        CP_COMMIT();

        // ---- x transpose + bf16 hi/lo convert, both row blocks ----
        #pragma unroll
        for (int it = 0; it < 4; it++) {
            int i = tid + it * 256;              // 1024 tasks: 2 rb x (cu 16 x n2 32)
            int rb = i >> 9;
            int ii = i & 511;
            int cu = ii & 15, n2 = ii >> 4;
            int c = ch * 32 + 2 * cu;
            const float* xp = x + ((size_t)(b * CIN + c)) * NSEQ + n0 + rb * 64 + 2 * n2;
            float2 va = *(const float2*)xp;
            float2 vb = *(const float2*)(xp + NSEQ);
            int pos = fpos(cu);
            uint32_t h0 = packbf(va.x, vb.x);
            uint32_t l0 = packbf(va.x - bf_lo_f(h0), vb.x - bf_hi_f(h0));
            uint32_t h1 = packbf(va.y, vb.y);
            uint32_t l1 = packbf(va.y - bf_lo_f(h1), vb.y - bf_hi_f(h1));
            uint32_t* bh = su + (rb ? PX_H1 : PX_H0);
            uint32_t* bl = su + (rb ? PX_L1 : PX_L0);
            bh[(2 * n2) * 24 + pos]     = h0;
            bl[(2 * n2) * 24 + pos]     = l0;
            bh[(2 * n2 + 1) * 24 + pos] = h1;
            bl[(2 * n2 + 1) * 24 + pos] = l1;
        }
        CP_WAIT(0);
        __syncthreads();

        // ---- 3-pass bf16 MMA, W fragments reused across both row blocks ----
        #pragma unroll
        for (int kt = 0; kt < 2; kt++) {
            const int ab = (16 * wr + l4) * 24 + kt * 8 + 2 * lm4;
            uint2 xa0 = *(const uint2*)(su + PX_H0 + ab);
            uint2 xb0 = *(const uint2*)(su + PX_H0 + ab + 8 * 24);
            uint2 la0 = *(const uint2*)(su + PX_L0 + ab);
            uint2 lb0 = *(const uint2*)(su + PX_L0 + ab + 8 * 24);
            uint2 xa1 = *(const uint2*)(su + PX_H1 + ab);
            uint2 xb1 = *(const uint2*)(su + PX_H1 + ab + 8 * 24);
            uint2 la1 = *(const uint2*)(su + PX_L1 + ab);
            uint2 lb1 = *(const uint2*)(su + PX_L1 + ab + 8 * 24);
            #pragma unroll
            for (int nt = 0; nt < 24; nt++) {
                const int bc = (jh * 192 + nt * 8 + l4) * 24 + kt * 8 + 2 * lm4;
                uint2 wh2 = *(const uint2*)&swh[bc];
                uint2 wl2 = *(const uint2*)&swl[bc];
                mma16bf(acc0[nt], xa0.x, xb0.x, xa0.y, xb0.y, wh2.x, wh2.y);
                mma16bf(acc0[nt], xa0.x, xb0.x, xa0.y, xb0.y, wl2.x, wl2.y);
                mma16bf(acc0[nt], la0.x, lb0.x, la0.y, lb0.y, wh2.x, wh2.y);
                mma16bf(acc1[nt], xa1.x, xb1.x, xa1.y, xb1.y, wh2.x, wh2.y);
                mma16bf(acc1[nt], xa1.x, xb1.x, xa1.y, xb1.y, wl2.x, wl2.y);
                mma16bf(acc1[nt], la1.x, lb1.x, la1.y, lb1.y, wh2.x, wh2.y);
            }
        }
    }

    // ---- epilogue: route both row blocks to g_q / g_khi+g_klo / g_v ----
    const int r0 = 16 * wr + l4;
    const bool vwrite = ((l4 & 1) == 0);

    #pragma unroll
    for (int rb = 0; rb < 2; rb++) {
        const size_t nrow0 = (size_t)b * NSEQ + n0 + rb * 64 + r0;
        const size_t nrow1 = nrow0 + 8;
        const size_t vb0 = ((size_t)b * (NSEQ / 2) + ((n0 + rb * 64 + r0) >> 1)) * DOUT;
        const size_t vb1 = ((size_t)b * (NSEQ / 2) + ((n0 + rb * 64 + r0 + 8) >> 1)) * DOUT;
        float4* acc = rb ? acc1 : acc0;

        if (jh == 0) {
            #pragma unroll
            for (int nt = 0; nt < 24; nt++) {
                float4 d = acc[nt];
                if (nt < 8) {
                    int j = nt * 8 + 2 * lm4;
                    *(float2*)&g_q[nrow0 * DKQ + j] = make_float2(d.x, d.y);
                    *(float2*)&g_q[nrow1 * DKQ + j] = make_float2(d.z, d.w);
                } else if (nt < 16) {
                    // K: fp16 hi/lo split, interleaved layout
                    int cu = (nt - 8) * 4 + lm4;
                    int pos = fpos(cu);
                    uint32_t h0 = packh(d.x, d.y);
                    uint32_t l0 = packh(d.x - h_lo_f(h0), d.y - h_hi_f(h0));
                    uint32_t h1 = packh(d.z, d.w);
                    uint32_t l1 = packh(d.z - h_lo_f(h1), d.w - h_hi_f(h1));
                    g_khi[nrow0 * 32 + pos] = h0;
                    g_klo[nrow0 * 32 + pos] = l0;
                    g_khi[nrow1 * 32 + pos] = h1;
                    g_klo[nrow1 * 32 + pos] = l1;
                } else {
                    int o = (nt - 16) * 8 + 2 * lm4;
                    float px = __uint_as_float(__shfl_down_sync(0xffffffffu, __float_as_uint(d.x), 4));
                    float py = __uint_as_float(__shfl_down_sync(0xffffffffu, __float_as_uint(d.y), 4));
                    float pz = __uint_as_float(__shfl_down_sync(0xffffffffu, __float_as_uint(d.z), 4));
                    float pw = __uint_as_float(__shfl_down_sync(0xffffffffu, __float_as_uint(d.w), 4));
                    if (vwrite) {
                        g_v[vb0 + o]     = packh(d.x, px);
                        g_v[vb0 + o + 1] = packh(d.y, py);
                        g_v[vb1 + o]     = packh(d.z, pz);
                        g_v[vb1 + o + 1] = packh(d.w, pw);
                    }
                }
            }
        } else {
            #pragma unroll
            for (int nt = 0; nt < 24; nt++) {
                float4 d = acc[nt];
                int o = 64 + nt * 8 + 2 * lm4;
                float px = __uint_as_float(__shfl_down_sync(0xffffffffu, __float_as_uint(d.x), 4));
                float py = __uint_as_float(__shfl_down_sync(0xffffffffu, __float_as_uint(d.y), 4));
                float pz = __uint_as_float(__shfl_down_sync(0xffffffffu, __float_as_uint(d.z), 4));
                float pw = __uint_as_float(__shfl_down_sync(0xffffffffu, __float_as_uint(d.w), 4));
                if (vwrite) {
                    g_v[vb0 + o]     = packh(d.x, px);
                    g_v[vb0 + o + 1] = packh(d.y, py);
                    g_v[vb1 + o]     = packh(d.z, pz);
                    g_v[vb1 + o + 1] = packh(d.w, pw);
                }
            }
        }
    }
}

// ==================== cp.async pipelined flash attention (fp16 QK 2-pass, fp16 PV) ====================
// SMEM (u32): sKh [64][40] @0, sKl @2560, sV [32][264] @5120, sP [128][36] @13568, lrow @18176
#define KH_O 0
#define KL_O 2560
#define V_O  5120
#define P_O  13568
#define L_O  18176
#define ATT_SMEM_U32 18304   // 73216 bytes

__device__ __forceinline__ void issue_k(int b, int k0, int tid, uint32_t smb) {
    #pragma unroll
    for (int it = 0; it < 4; it++) {
        int i = tid + it * 256;              // 1024 chunks: 2 arrays x 64 rows x 8
        int arr = i >> 9, r = (i >> 3) & 63, c = i & 7;
        const uint32_t* src = (arr ? g_klo : g_khi) +
                              ((size_t)b * NSEQ + k0 + r) * 32 + c * 4;
        uint32_t dst = smb + (uint32_t)(arr ? KL_O : KH_O) * 4 + r * 160 + c * 16;
        cp_async16(dst, src);
    }
}
__device__ __forceinline__ void issue_v(int b, int k0, int tid, uint32_t smb) {
    const uint32_t* vg = g_v + ((size_t)b * (NSEQ / 2) + k0 / 2) * DOUT;
    #pragma unroll
    for (int it = 0; it < 8; it++) {
        int i = tid + it * 256;              // 2048 chunks: 32 kpair rows x 64
        int r = i >> 6, c4 = i & 63;
        uint32_t dst = smb + (uint32_t)V_O * 4 + r * 1056 + c4 * 16;
        cp_async16(dst, vg + (size_t)r * DOUT + 4 * c4);
    }
}

__global__ __launch_bounds__(256, 1) void attn_mma(float* __restrict__ out) {
    extern __shared__ uint32_t su[];
    const uint32_t* sKh = su + KH_O;
    const uint32_t* sKl = su + KL_O;
    const uint32_t* sVu = su + V_O;
    uint32_t* sPu = su + P_O;
    float* lrow = (float*)(su + L_O);
    float* sQf = (float*)(su + V_O);   // prologue staging
    const uint32_t smb = smem_u32(su);

    const int tid = threadIdx.x;
    const int w   = tid >> 5;
    const int ln  = tid & 31;
    const int l4  = ln >> 2;
    const int lm4 = ln & 3;
    const int rg  = w >> 1;
    const int cg  = w & 1;
    const int b   = blockIdx.y;
    const int n0  = blockIdx.x * BM;

    issue_k(b, 0, tid, smb);
    CP_COMMIT();

    // ---- stage Q (fp32) through V region, build fp16 A-fragments (single array) ----
    uint32_t qf[4][4];
    {
        const float* qg = g_q + ((size_t)b * NSEQ + n0) * DKQ;
        #pragma unroll
        for (int it = 0; it < 8; it++) {
            int i = tid + it * 256;
            int r = i >> 4, c4 = i & 15;
            *(float4*)&sQf[r * 68 + 4 * c4] = *(const float4*)&qg[(size_t)r * DKQ + 4 * c4];
        }
        __syncthreads();
        const int r0 = (w * 16 + l4) * 68;
        const int r1 = r0 + 8 * 68;
        #pragma unroll
        for (int kt = 0; kt < 4; kt++) {
            const int d0 = 16 * kt + 2 * lm4;
            float2 va = *(const float2*)&sQf[r0 + d0];
            float2 vb = *(const float2*)&sQf[r1 + d0];
            float2 vc = *(const float2*)&sQf[r0 + d0 + 8];
            float2 vd = *(const float2*)&sQf[r1 + d0 + 8];
            qf[kt][0] = packh(va.x, va.y);
            qf[kt][1] = packh(vb.x, vb.y);
            qf[kt][2] = packh(vc.x, vc.y);
            qf[kt][3] = packh(vd.x, vd.y);
        }
        __syncthreads();   // done reading staging before V(0) overwrites it
    }
    issue_v(b, 0, tid, smb);
    CP_COMMIT();

    float4 O[32];
    #pragma unroll
    for (int nt = 0; nt < 32; nt++) O[nt] = make_float4(0.f, 0.f, 0.f, 0.f);
    float lsumA = 0.f, lsumB = 0.f;

    const int prow = (w * 16 + l4) * 36;

    #pragma unroll 1
    for (int t = 0; t < NTILES; t++) {
        CP_WAIT(1);
        __syncthreads();

        // ---- S = q_f16 * (Khi + Klo)  (fp16 2-pass) ----
        float4 S[8];
        #pragma unroll
        for (int nt = 0; nt < 8; nt++) S[nt] = make_float4(0.f, 0.f, 0.f, 0.f);

        #pragma unroll
        for (int kt = 0; kt < 4; kt++) {
            #pragma unroll
            for (int nt = 0; nt < 8; nt++) {
                const int bc = (nt * 8 + l4) * 40 + kt * 8 + 2 * lm4;
                uint2 kh = *(const uint2*)&sKh[bc];
                uint2 kl = *(const uint2*)&sKl[bc];
                mma16h(S[nt], qf[kt][0], qf[kt][1], qf[kt][2], qf[kt][3], kh.x, kh.y);
                mma16h(S[nt], qf[kt][0], qf[kt][1], qf[kt][2], qf[kt][3], kl.x, kl.y);
            }
        }

        // ---- softmax (log2 domain); P -> fp16 pairs; lsum fp32 ----
        #pragma unroll
        for (int nt = 0; nt < 8; nt++) {
            float p0 = fast_exp2(S[nt].x);
            float p1 = fast_exp2(S[nt].y);
            float p2 = fast_exp2(S[nt].z);
            float p3 = fast_exp2(S[nt].w);
            lsumA += p0 + p1;
            lsumB += p2 + p3;
            const int pc = prow + nt * 4 + lm4;
            sPu[pc]          = packh(p0, p1);
            sPu[pc + 8 * 36] = packh(p2, p3);
        }
        __syncthreads();

        if (t + 1 < NTILES) issue_k(b, (t + 1) * BK, tid, smb);
        CP_COMMIT();

        CP_WAIT(1);
        __syncthreads();

        // ---- O += P * V (fp16) ----
        #pragma unroll
        for (int kt = 0; kt < 4; kt++) {
            const int ac0 = (32 * rg + l4) * 36 + 8 * kt + lm4;
            const int ac1 = ac0 + 16 * 36;
            uint32_t pa0 = sPu[ac0],     pa1 = sPu[ac0 + 8 * 36];
            uint32_t pa2 = sPu[ac0 + 4], pa3 = sPu[ac0 + 8 * 36 + 4];
            uint32_t pb0 = sPu[ac1],     pb1 = sPu[ac1 + 8 * 36];
            uint32_t pb2 = sPu[ac1 + 4], pb3 = sPu[ac1 + 8 * 36 + 4];
            const int v0b = (8 * kt + lm4) * 264 + 128 * cg + l4;
            const int v1b = v0b + 4 * 264;
            #pragma unroll
            for (int nt = 0; nt < 16; nt++) {
                uint32_t v0 = sVu[v0b + nt * 8];
                uint32_t v1 = sVu[v1b + nt * 8];
                mma16h(O[nt],      pa0, pa1, pa2, pa3, v0, v1);
                mma16h(O[16 + nt], pb0, pb1, pb2, pb3, v0, v1);
            }
        }
        __syncthreads();

        if (t + 1 < NTILES) issue_v(b, (t + 1) * BK, tid, smb);
        CP_COMMIT();
    }

    // ---- epilogue ----
    lsumA += __shfl_xor_sync(0xffffffffu, lsumA, 1);
    lsumA += __shfl_xor_sync(0xffffffffu, lsumA, 2);
    lsumB += __shfl_xor_sync(0xffffffffu, lsumB, 1);
    lsumB += __shfl_xor_sync(0xffffffffu, lsumB, 2);
    if (lm4 == 0) {
        lrow[w * 16 + l4]     = lsumA;
        lrow[w * 16 + l4 + 8] = lsumB;
    }
    __syncthreads();

    #pragma unroll
    for (int mb = 0; mb < 2; mb++) {
        const int rbase = 32 * rg + 16 * mb + l4;
        float invA = 1.0f / lrow[rbase];
        float invB = 1.0f / lrow[rbase + 8];
        float* ob = out + (size_t)b * DOUT * NSEQ + n0 + rbase;
        #pragma unroll
        for (int nt = 0; nt < 16; nt++) {
            int o = 128 * cg + nt * 8 + 2 * lm4;
            float4 v = O[mb * 16 + nt];
            ob[(size_t)o * NSEQ]           = v.x * invA;
            ob[(size_t)(o + 1) * NSEQ]     = v.y * invA;
            ob[(size_t)o * NSEQ + 8]       = v.z * invB;
            ob[(size_t)(o + 1) * NSEQ + 8] = v.w * invB;
        }
    }
}

extern "C" void kernel_launch(void* const* d_in, const int* in_sizes, int n_in,
                              void* d_out, int out_size) {
    (void)in_sizes; (void)n_in; (void)out_size;
    const float* x  = (const float*)d_in[0];
    const float* Wq = (const float*)d_in[1];
    const float* Wk = (const float*)d_in[2];
    const float* Wv = (const float*)d_in[3];
    float* out = (float*)d_out;

    cudaFuncSetAttribute(proj_tc, cudaFuncAttributeMaxDynamicSharedMemorySize,
                         PROJ_SMEM_U32 * (int)sizeof(uint32_t));
    cudaFuncSetAttribute(attn_mma, cudaFuncAttributeMaxDynamicSharedMemorySize,
                         ATT_SMEM_U32 * (int)sizeof(uint32_t));

    w_prep<<<192, 256>>>(Wq, Wk, Wv);

    dim3 gp(NSEQ / 128, BATCH);
    proj_tc<<<gp, 256, PROJ_SMEM_U32 * sizeof(uint32_t)>>>(x);

    dim3 ga(NSEQ / BM, BATCH);
    attn_mma<<<ga, 256, ATT_SMEM_U32 * sizeof(uint32_t)>>>(out);
}

// round 17
// speedup vs baseline: 1.1952x; 1.1413x over previous
#include <cuda_runtime.h>
#include <cuda_bf16.h>
#include <cuda_fp16.h>
#include <math.h>
#include <stdint.h>

// Problem constants
#define BATCH 8
#define CIN   256
#define NSEQ  4096
#define DKQ   64
#define DOUT  256

// Attention tiling
#define BM 128
#define BK 64
#define NTILES (NSEQ / BK)

// Scratch (device globals)
__device__ float    g_q[(size_t)BATCH * NSEQ * DKQ];      // [b][n][64], fp32, scaled log2e/8
__device__ uint32_t g_k[(size_t)BATCH * NSEQ * 32];       // [b][n][32] fp16x2, RN, interleaved
__device__ uint32_t g_v[(size_t)BATCH * (NSEQ/2) * DOUT]; // [b][kp][ch] fp16x2 (rows 2kp,2kp+1)
__device__ uint32_t g_wh[8 * 384 * 16];                   // W bf16 hi, [chunk][j][16 u32]
__device__ uint32_t g_wl[8 * 384 * 16];                   // W bf16 lo

__device__ __forceinline__ float fast_exp2(float x) {
    float r;
    asm("ex2.approx.ftz.f32 %0, %1;" : "=f"(r) : "f"(x));
    return r;
}
__device__ __forceinline__ uint32_t smem_u32(const void* p) {
    uint32_t a;
    asm("{ .reg .u64 t; cvta.to.shared.u64 t, %1; cvt.u32.u64 %0, t; }" : "=r"(a) : "l"(p));
    return a;
}
__device__ __forceinline__ void cp_async16(uint32_t dst, const void* src) {
    asm volatile("cp.async.cg.shared.global [%0], [%1], 16;" :: "r"(dst), "l"(src));
}
#define CP_COMMIT() asm volatile("cp.async.commit_group;" ::: "memory")
#define CP_WAIT(N)  asm volatile("cp.async.wait_group %0;" :: "n"(N) : "memory")

// bf16 pack
__device__ __forceinline__ uint32_t packbf(float lo, float hi) {
    __nv_bfloat162 h2 = __floats2bfloat162_rn(lo, hi);
    return *(uint32_t*)&h2;
}
__device__ __forceinline__ float bf_lo_f(uint32_t p) { return __uint_as_float(p << 16); }
__device__ __forceinline__ float bf_hi_f(uint32_t p) { return __uint_as_float(p & 0xFFFF0000u); }
// fp16 pack
__device__ __forceinline__ uint32_t packh(float lo, float hi) {
    __half2 h2 = __floats2half2_rn(lo, hi);
    return *(uint32_t*)&h2;
}

// fragment interleave position for u32 column index (cu in [0,32))
__device__ __forceinline__ int fpos(int cu) {
    return ((cu >> 3) << 3) + ((cu & 3) << 1) + ((cu >> 2) & 1);
}

// m16n8k16 bf16 mma (proj)
__device__ __forceinline__ void mma16bf(float4& d,
                                        uint32_t a0, uint32_t a1, uint32_t a2, uint32_t a3,
                                        uint32_t b0, uint32_t b1) {
    asm("mma.sync.aligned.m16n8k16.row.col.f32.bf16.bf16.f32 "
        "{%0,%1,%2,%3}, {%4,%5,%6,%7}, {%8,%9}, {%0,%1,%2,%3};"
        : "+f"(d.x), "+f"(d.y), "+f"(d.z), "+f"(d.w)
        : "r"(a0), "r"(a1), "r"(a2), "r"(a3), "r"(b0), "r"(b1));
}
// m16n8k16 fp16 mma (QK + PV)
__device__ __forceinline__ void mma16h(float4& d,
                                       uint32_t a0, uint32_t a1, uint32_t a2, uint32_t a3,
                                       uint32_t b0, uint32_t b1) {
    asm("mma.sync.aligned.m16n8k16.row.col.f32.f16.f16.f32 "
        "{%0,%1,%2,%3}, {%4,%5,%6,%7}, {%8,%9}, {%0,%1,%2,%3};"
        : "+f"(d.x), "+f"(d.y), "+f"(d.z), "+f"(d.w)
        : "r"(a0), "r"(a1), "r"(a2), "r"(a3), "r"(b0), "r"(b1));
}

// ==================== W prep: fp32 -> bf16 hi/lo fragment layout ====================
__global__ __launch_bounds__(256) void w_prep(const float* __restrict__ Wq,
                                              const float* __restrict__ Wk,
                                              const float* __restrict__ Wv) {
    int i = blockIdx.x * 256 + threadIdx.x;   // 49152 tasks
    int cu = i & 15;
    int j  = (i >> 4) % 384;
    int ch = i / 6144;
    int c  = ch * 32 + 2 * cu;

    const float* wrow;
    float s;
    if (j < 64)       { wrow = Wq + (size_t)j * CIN;        s = 0.125f * 1.4426950408889634f; }
    else if (j < 128) { wrow = Wk + (size_t)(j - 64) * CIN; s = 1.0f; }
    else              { wrow = Wv + (size_t)(j - 128) * CIN; s = 1.0f; }

    float va = wrow[c] * s;
    float vb = wrow[c + 1] * s;
    uint32_t h = packbf(va, vb);
    uint32_t l = packbf(va - bf_lo_f(h), vb - bf_hi_f(h));
    size_t dst = ((size_t)ch * 384 + j) * 16 + fpos(cu);
    g_wh[dst] = h;
    g_wl[dst] = l;
}

// ==================== tensor-core projection (64 rows/CTA, R15 body) ====================
// SMEM (u32): swh [384][24] @0, swl @9216, sxh [64][24] @18432, sxl @19968.
#define PW_H 0
#define PW_L 9216
#define PX_H 18432
#define PX_L 19968
#define PROJ_SMEM_U32 21504   // 86016 bytes

__global__ __launch_bounds__(256, 1) void proj_tc(const float* __restrict__ x) {
    extern __shared__ uint32_t su[];
    uint32_t* swh = su + PW_H;
    uint32_t* swl = su + PW_L;
    uint32_t* sxh = su + PX_H;
    uint32_t* sxl = su + PX_L;
    const uint32_t smb = smem_u32(su);

    const int tid = threadIdx.x;
    const int w   = tid >> 5;
    const int ln  = tid & 31;
    const int l4  = ln >> 2;
    const int lm4 = ln & 3;
    const int wr  = w & 3;
    const int jh  = w >> 2;
    const int b   = blockIdx.y;
    const int n0  = blockIdx.x * 64;

    float4 acc[24];
    #pragma unroll
    for (int nt = 0; nt < 24; nt++) acc[nt] = make_float4(0.f, 0.f, 0.f, 0.f);

    #pragma unroll 1
    for (int ch = 0; ch < 8; ch++) {
        __syncthreads();

        #pragma unroll
        for (int it = 0; it < 12; it++) {
            int i = tid + it * 256;              // 3072: 2 arrays x 384 rows x 4 q4
            int arr = (i >= 1536);
            int ii  = i - (arr ? 1536 : 0);
            int r   = ii >> 2;
            int q4  = ii & 3;
            const uint32_t* src = (arr ? g_wl : g_wh) + ((size_t)ch * 384 + r) * 16 + q4 * 4;
            uint32_t dst = smb + (uint32_t)((arr ? PW_L : PW_H) + r * 24 + q4 * 4) * 4;
            cp_async16(dst, src);
        }
        CP_COMMIT();

        #pragma unroll
        for (int it = 0; it < 2; it++) {
            int i = tid + it * 256;              // 512 tasks: cu 16 x n2 32
            int cu = i & 15, n2 = i >> 4;
            int c = ch * 32 + 2 * cu;
            const float* xp = x + ((size_t)(b * CIN + c)) * NSEQ + n0 + 2 * n2;
            float2 va = *(const float2*)xp;
            float2 vb = *(const float2*)(xp + NSEQ);
            int pos = fpos(cu);
            uint32_t h0 = packbf(va.x, vb.x);
            uint32_t l0 = packbf(va.x - bf_lo_f(h0), vb.x - bf_hi_f(h0));
            uint32_t h1 = packbf(va.y, vb.y);
            uint32_t l1 = packbf(va.y - bf_lo_f(h1), vb.y - bf_hi_f(h1));
            sxh[(2 * n2) * 24 + pos]     = h0;
            sxl[(2 * n2) * 24 + pos]     = l0;
            sxh[(2 * n2 + 1) * 24 + pos] = h1;
            sxl[(2 * n2 + 1) * 24 + pos] = l1;
        }
        CP_WAIT(0);
        __syncthreads();

        #pragma unroll
        for (int kt = 0; kt < 2; kt++) {
            const int ab = (16 * wr + l4) * 24 + kt * 8 + 2 * lm4;
            uint2 xa = *(const uint2*)&sxh[ab];
            uint2 xb = *(const uint2*)&sxh[ab + 8 * 24];
            uint2 la = *(const uint2*)&sxl[ab];
            uint2 lb = *(const uint2*)&sxl[ab + 8 * 24];
            #pragma unroll
            for (int nt = 0; nt < 24; nt++) {
                const int bc = (jh * 192 + nt * 8 + l4) * 24 + kt * 8 + 2 * lm4;
                uint2 wh2 = *(const uint2*)&swh[bc];
                uint2 wl2 = *(const uint2*)&swl[bc];
                mma16bf(acc[nt], xa.x, xb.x, xa.y, xb.y, wh2.x, wh2.y);
                mma16bf(acc[nt], xa.x, xb.x, xa.y, xb.y, wl2.x, wl2.y);
                mma16bf(acc[nt], la.x, lb.x, la.y, lb.y, wh2.x, wh2.y);
            }
        }
    }

    // ---- epilogue: route to g_q / g_k(fp16 single) / g_v(fp16 kpair-packed) ----
    const int r0 = 16 * wr + l4;
    const size_t nrow0 = (size_t)b * NSEQ + n0 + r0;
    const size_t nrow1 = nrow0 + 8;
    const size_t vb0 = ((size_t)b * (NSEQ / 2) + ((n0 + r0) >> 1)) * DOUT;
    const size_t vb1 = ((size_t)b * (NSEQ / 2) + ((n0 + r0 + 8) >> 1)) * DOUT;
    const bool vwrite = ((l4 & 1) == 0);

    if (jh == 0) {
        #pragma unroll
        for (int nt = 0; nt < 24; nt++) {
            float4 d = acc[nt];
            if (nt < 8) {
                int j = nt * 8 + 2 * lm4;
                *(float2*)&g_q[nrow0 * DKQ + j] = make_float2(d.x, d.y);
                *(float2*)&g_q[nrow1 * DKQ + j] = make_float2(d.z, d.w);
            } else if (nt < 16) {
                // K: single fp16 RN, interleaved layout
                int cu = (nt - 8) * 4 + lm4;
                int pos = fpos(cu);
                g_k[nrow0 * 32 + pos] = packh(d.x, d.y);
                g_k[nrow1 * 32 + pos] = packh(d.z, d.w);
            } else {
                int o = (nt - 16) * 8 + 2 * lm4;
                float px = __uint_as_float(__shfl_down_sync(0xffffffffu, __float_as_uint(d.x), 4));
                float py = __uint_as_float(__shfl_down_sync(0xffffffffu, __float_as_uint(d.y), 4));
                float pz = __uint_as_float(__shfl_down_sync(0xffffffffu, __float_as_uint(d.z), 4));
                float pw = __uint_as_float(__shfl_down_sync(0xffffffffu, __float_as_uint(d.w), 4));
                if (vwrite) {
                    g_v[vb0 + o]     = packh(d.x, px);
                    g_v[vb0 + o + 1] = packh(d.y, py);
                    g_v[vb1 + o]     = packh(d.z, pz);
                    g_v[vb1 + o + 1] = packh(d.w, pw);
                }
            }
        }
    } else {
        #pragma unroll
        for (int nt = 0; nt < 24; nt++) {
            float4 d = acc[nt];
            int o = 64 + nt * 8 + 2 * lm4;
            float px = __uint_as_float(__shfl_down_sync(0xffffffffu, __float_as_uint(d.x), 4));
            float py = __uint_as_float(__shfl_down_sync(0xffffffffu, __float_as_uint(d.y), 4));
            float pz = __uint_as_float(__shfl_down_sync(0xffffffffu, __float_as_uint(d.z), 4));
            float pw = __uint_as_float(__shfl_down_sync(0xffffffffu, __float_as_uint(d.w), 4));
            if (vwrite) {
                g_v[vb0 + o]     = packh(d.x, px);
                g_v[vb0 + o + 1] = packh(d.y, py);
                g_v[vb1 + o]     = packh(d.z, pz);
                g_v[vb1 + o + 1] = packh(d.w, pw);
            }
        }
    }
}

// ==================== cp.async pipelined flash attention (fp16 QK 1-pass, fp16 PV) ====================
// SMEM (u32): sK [64][40] @0 (2560), sV [32][264] @2560 (8448),
//             sP [128][36] @11008 (4608), lrow @15616 (128)
// Q staging (prologue only): floats at u32 offset 2560 (needs 8704 <= 13056 free)
#define K_O  0
#define V_O  2560
#define P_O  11008
#define L_O  15616
#define ATT_SMEM_U32 15744   // 62976 bytes

__device__ __forceinline__ void issue_k(int b, int k0, int tid, uint32_t smb) {
    #pragma unroll
    for (int it = 0; it < 2; it++) {
        int i = tid + it * 256;              // 512 chunks: 64 rows x 8
        int r = i >> 3, c = i & 7;
        const uint32_t* src = g_k + ((size_t)b * NSEQ + k0 + r) * 32 + c * 4;
        uint32_t dst = smb + (uint32_t)K_O * 4 + r * 160 + c * 16;
        cp_async16(dst, src);
    }
}
__device__ __forceinline__ void issue_v(int b, int k0, int tid, uint32_t smb) {
    const uint32_t* vg = g_v + ((size_t)b * (NSEQ / 2) + k0 / 2) * DOUT;
    #pragma unroll
    for (int it = 0; it < 8; it++) {
        int i = tid + it * 256;              // 2048 chunks: 32 kpair rows x 64
        int r = i >> 6, c4 = i & 63;
        uint32_t dst = smb + (uint32_t)V_O * 4 + r * 1056 + c4 * 16;
        cp_async16(dst, vg + (size_t)r * DOUT + 4 * c4);
    }
}

__global__ __launch_bounds__(256, 1) void attn_mma(float* __restrict__ out) {
    extern __shared__ uint32_t su[];
    const uint32_t* sK  = su + K_O;
    const uint32_t* sVu = su + V_O;
    uint32_t* sPu = su + P_O;
    float* lrow = (float*)(su + L_O);
    float* sQf = (float*)(su + V_O);   // prologue staging (spans V+P region)
    const uint32_t smb = smem_u32(su);

    const int tid = threadIdx.x;
    const int w   = tid >> 5;
    const int ln  = tid & 31;
    const int l4  = ln >> 2;
    const int lm4 = ln & 3;
    const int rg  = w >> 1;
    const int cg  = w & 1;
    const int b   = blockIdx.y;
    const int n0  = blockIdx.x * BM;

    issue_k(b, 0, tid, smb);
    CP_COMMIT();

    // ---- stage Q (fp32) through V+P region, build fp16 A-fragments ----
    uint32_t qf[4][4];
    {
        const float* qg = g_q + ((size_t)b * NSEQ + n0) * DKQ;
        #pragma unroll
        for (int it = 0; it < 8; it++) {
            int i = tid + it * 256;
            int r = i >> 4, c4 = i & 15;
            *(float4*)&sQf[r * 68 + 4 * c4] = *(const float4*)&qg[(size_t)r * DKQ + 4 * c4];
        }
        __syncthreads();
        const int r0 = (w * 16 + l4) * 68;
        const int r1 = r0 + 8 * 68;
        #pragma unroll
        for (int kt = 0; kt < 4; kt++) {
            const int d0 = 16 * kt + 2 * lm4;
            float2 va = *(const float2*)&sQf[r0 + d0];
            float2 vb = *(const float2*)&sQf[r1 + d0];
            float2 vc = *(const float2*)&sQf[r0 + d0 + 8];
            float2 vd = *(const float2*)&sQf[r1 + d0 + 8];
            qf[kt][0] = packh(va.x, va.y);
            qf[kt][1] = packh(vb.x, vb.y);
            qf[kt][2] = packh(vc.x, vc.y);
            qf[kt][3] = packh(vd.x, vd.y);
        }
        __syncthreads();   // done reading staging before V(0) overwrites it
    }
    issue_v(b, 0, tid, smb);
    CP_COMMIT();

    float4 O[32];
    #pragma unroll
    for (int nt = 0; nt < 32; nt++) O[nt] = make_float4(0.f, 0.f, 0.f, 0.f);
    float lsumA = 0.f, lsumB = 0.f;

    const int prow = (w * 16 + l4) * 36;

    #pragma unroll 1
    for (int t = 0; t < NTILES; t++) {
        // K(t) ready (V(t) may still be in flight)
        CP_WAIT(1);
        __syncthreads();

        // ---- S = q_f16 * k_f16  (single pass) ----
        float4 S[8];
        #pragma unroll
        for (int nt = 0; nt < 8; nt++) S[nt] = make_float4(0.f, 0.f, 0.f, 0.f);

        #pragma unroll
        for (int kt = 0; kt < 4; kt++) {
            #pragma unroll
            for (int nt = 0; nt < 8; nt++) {
                const int bc = (nt * 8 + l4) * 40 + kt * 8 + 2 * lm4;
                uint2 kk = *(const uint2*)&sK[bc];
                mma16h(S[nt], qf[kt][0], qf[kt][1], qf[kt][2], qf[kt][3], kk.x, kk.y);
            }
        }

        // ---- softmax (log2 domain); P -> fp16 pairs; lsum fp32 ----
        #pragma unroll
        for (int nt = 0; nt < 8; nt++) {
            float p0 = fast_exp2(S[nt].x);
            float p1 = fast_exp2(S[nt].y);
            float p2 = fast_exp2(S[nt].z);
            float p3 = fast_exp2(S[nt].w);
            lsumA += p0 + p1;
            lsumB += p2 + p3;
            const int pc = prow + nt * 4 + lm4;
            sPu[pc]          = packh(p0, p1);
            sPu[pc + 8 * 36] = packh(p2, p3);
        }
        __syncthreads();   // QK done with K; P visible block-wide

        if (t + 1 < NTILES) issue_k(b, (t + 1) * BK, tid, smb);
        CP_COMMIT();

        // V(t) ready
        CP_WAIT(1);
        __syncthreads();

        // ---- O += P * V (fp16) : rows [32rg,+32) x channels [128cg,+128) ----
        #pragma unroll
        for (int kt = 0; kt < 4; kt++) {
            const int ac0 = (32 * rg + l4) * 36 + 8 * kt + lm4;
            const int ac1 = ac0 + 16 * 36;
            uint32_t pa0 = sPu[ac0],     pa1 = sPu[ac0 + 8 * 36];
            uint32_t pa2 = sPu[ac0 + 4], pa3 = sPu[ac0 + 8 * 36 + 4];
            uint32_t pb0 = sPu[ac1],     pb1 = sPu[ac1 + 8 * 36];
            uint32_t pb2 = sPu[ac1 + 4], pb3 = sPu[ac1 + 8 * 36 + 4];
            const int v0b = (8 * kt + lm4) * 264 + 128 * cg + l4;
            const int v1b = v0b + 4 * 264;
            #pragma unroll
            for (int nt = 0; nt < 16; nt++) {
                uint32_t v0 = sVu[v0b + nt * 8];
                uint32_t v1 = sVu[v1b + nt * 8];
                mma16h(O[nt],      pa0, pa1, pa2, pa3, v0, v1);
                mma16h(O[16 + nt], pb0, pb1, pb2, pb3, v0, v1);
            }
        }
        __syncthreads();   // PV done with V

        if (t + 1 < NTILES) issue_v(b, (t + 1) * BK, tid, smb);
        CP_COMMIT();
    }

    // ---- epilogue ----
    lsumA += __shfl_xor_sync(0xffffffffu, lsumA, 1);
    lsumA += __shfl_xor_sync(0xffffffffu, lsumA, 2);
    lsumB += __shfl_xor_sync(0xffffffffu, lsumB, 1);
    lsumB += __shfl_xor_sync(0xffffffffu, lsumB, 2);
    if (lm4 == 0) {
        lrow[w * 16 + l4]     = lsumA;
        lrow[w * 16 + l4 + 8] = lsumB;
    }
    __syncthreads();

    #pragma unroll
    for (int mb = 0; mb < 2; mb++) {
        const int rbase = 32 * rg + 16 * mb + l4;
        float invA = 1.0f / lrow[rbase];
        float invB = 1.0f / lrow[rbase + 8];
        float* ob = out + (size_t)b * DOUT * NSEQ + n0 + rbase;
        #pragma unroll
        for (int nt = 0; nt < 16; nt++) {
            int o = 128 * cg + nt * 8 + 2 * lm4;
            float4 v = O[mb * 16 + nt];
            ob[(size_t)o * NSEQ]           = v.x * invA;
            ob[(size_t)(o + 1) * NSEQ]     = v.y * invA;
            ob[(size_t)o * NSEQ + 8]       = v.z * invB;
            ob[(size_t)(o + 1) * NSEQ + 8] = v.w * invB;
        }
    }
}

extern "C" void kernel_launch(void* const* d_in, const int* in_sizes, int n_in,
                              void* d_out, int out_size) {
    (void)in_sizes; (void)n_in; (void)out_size;
    const float* x  = (const float*)d_in[0];
    const float* Wq = (const float*)d_in[1];
    const float* Wk = (const float*)d_in[2];
    const float* Wv = (const float*)d_in[3];
    float* out = (float*)d_out;

    cudaFuncSetAttribute(proj_tc, cudaFuncAttributeMaxDynamicSharedMemorySize,
                         PROJ_SMEM_U32 * (int)sizeof(uint32_t));
    cudaFuncSetAttribute(attn_mma, cudaFuncAttributeMaxDynamicSharedMemorySize,
                         ATT_SMEM_U32 * (int)sizeof(uint32_t));

    w_prep<<<192, 256>>>(Wq, Wk, Wv);

    dim3 gp(NSEQ / 64, BATCH);
    proj_tc<<<gp, 256, PROJ_SMEM_U32 * sizeof(uint32_t)>>>(x);

    dim3 ga(NSEQ / BM, BATCH);
    attn_mma<<<ga, 256, ATT_SMEM_U32 * sizeof(uint32_t)>>>(out);
}